// round 4
// baseline (speedup 1.0000x reference)
#include <cuda_runtime.h>
#include <float.h>

#define BB    8
#define NN    2048
#define KK    16
#define CIN   64
#define COUT  128
#define BN_EPS 1e-3f
#define LARGE_DIST 1e9f

#define SPLIT 8
#define CAND  (NN / SPLIT)   // 256
#define NPTS  (BB * NN)      // 16384

#define BNT 128
#define BKT 16

// ---- global scratch -------------------------------------------------------
__device__ float g_pd[NPTS * SPLIT * KK];
__device__ int   g_pi[NPTS * SPLIT * KK];
__device__ int   g_idx[NPTS * KK];
__device__ float g_h[(size_t)NPTS * 512];
__device__ float g_X[(size_t)NPTS * 256];
__device__ float g_lift[(size_t)NPTS * 16 * 64];
__device__ float g_tr[(size_t)NPTS * 1024];

// ---- packed fp32x2 helpers ------------------------------------------------
__device__ __forceinline__ unsigned long long pack2(float lo, float hi) {
    unsigned long long r;
    asm("mov.b64 %0, {%1, %2};" : "=l"(r) : "f"(lo), "f"(hi));
    return r;
}
__device__ __forceinline__ float2 unpack2(unsigned long long v) {
    float2 r;
    asm("mov.b64 {%0, %1}, %2;" : "=f"(r.x), "=f"(r.y) : "l"(v));
    return r;
}
__device__ __forceinline__ void ffma2(unsigned long long& a,
                                      unsigned long long x,
                                      unsigned long long y) {
    asm("fma.rn.f32x2 %0, %1, %2, %0;" : "+l"(a) : "l"(x), "l"(y));
}
__device__ __forceinline__ unsigned long long add2(unsigned long long x,
                                                   unsigned long long y) {
    unsigned long long r;
    asm("add.rn.f32x2 %0, %1, %2;" : "=l"(r) : "l"(x), "l"(y));
    return r;
}
__device__ __forceinline__ unsigned long long mul2(unsigned long long x,
                                                   unsigned long long y) {
    unsigned long long r;
    asm("mul.rn.f32x2 %0, %1, %2;" : "=l"(r) : "l"(x), "l"(y));
    return r;
}

// ---------------------------------------------------------------------------
// KNN
// ---------------------------------------------------------------------------
__device__ __forceinline__ void insert16(float* bd, int* bi, float d, int j) {
    bd[KK - 1] = d; bi[KK - 1] = j;
#pragma unroll
    for (int t = KK - 1; t > 0; --t) {
        if (bd[t] < bd[t - 1]) {
            float td = bd[t]; bd[t] = bd[t - 1]; bd[t - 1] = td;
            int   ti = bi[t]; bi[t] = bi[t - 1]; bi[t - 1] = ti;
        }
    }
}

__global__ __launch_bounds__(128)
void knn_part(const float* __restrict__ xyz,
              float* __restrict__ pd, int* __restrict__ pi) {
    __shared__ float s_nx[NN], s_ny[NN], s_nz[NN], s_pen[NN];
    const int tid = threadIdx.x;
    const int qg  = blockIdx.x >> 3;
    const int sp  = blockIdx.x & 7;
    const int g   = qg * 128 + tid;
    const int b   = g >> 11;
    const int n   = g & (NN - 1);

    for (int j = tid; j < NN; j += 128) {
        const float* p = xyz + ((size_t)b * NN + j) * 3;
        float x = p[0], y = p[1], z = p[2];
        bool v = (x != 0.0f || y != 0.0f || z != 0.0f);
        s_nx[j] = -x; s_ny[j] = -y; s_nz[j] = -z;
        s_pen[j] = v ? 0.0f : LARGE_DIST;
    }
    __syncthreads();

    const float* qp = xyz + ((size_t)b * NN + n) * 3;
    unsigned long long qx2 = pack2(qp[0], qp[0]);
    unsigned long long qy2 = pack2(qp[1], qp[1]);
    unsigned long long qz2 = pack2(qp[2], qp[2]);

    float bd[KK]; int bi[KK];
#pragma unroll
    for (int t = 0; t < KK; t++) { bd[t] = FLT_MAX; bi[t] = 0; }

    const unsigned long long* px2 = (const unsigned long long*)s_nx + sp * (CAND / 2);
    const unsigned long long* py2 = (const unsigned long long*)s_ny + sp * (CAND / 2);
    const unsigned long long* pz2 = (const unsigned long long*)s_nz + sp * (CAND / 2);
    const unsigned long long* pp2 = (const unsigned long long*)s_pen + sp * (CAND / 2);
    const int jbase = sp * CAND;

#pragma unroll 8
    for (int jj = 0; jj < CAND / 2; jj++) {
        unsigned long long dx2 = add2(qx2, px2[jj]);
        unsigned long long dy2 = add2(qy2, py2[jj]);
        unsigned long long dz2 = add2(qz2, pz2[jj]);
        unsigned long long d2  = mul2(dx2, dx2);
        ffma2(d2, dy2, dy2);
        ffma2(d2, dz2, dz2);
        d2 = add2(d2, pp2[jj]);
        float2 d = unpack2(d2);
        if (fminf(d.x, d.y) < bd[KK - 1]) {
            if (d.x < bd[KK - 1]) insert16(bd, bi, d.x, jbase + 2 * jj);
            if (d.y < bd[KK - 1]) insert16(bd, bi, d.y, jbase + 2 * jj + 1);
        }
    }

    float* po = pd + ((size_t)g * SPLIT + sp) * KK;
    int*   io = pi + ((size_t)g * SPLIT + sp) * KK;
#pragma unroll
    for (int t = 0; t < KK; t++) { po[t] = bd[t]; io[t] = bi[t]; }
}

__global__ __launch_bounds__(128)
void knn_merge(const float* __restrict__ pd, const int* __restrict__ pi,
               int* __restrict__ idx_out) {
    const int g = blockIdx.x * 128 + threadIdx.x;
    float bd[KK]; int bi[KK];
#pragma unroll
    for (int t = 0; t < KK; t++) { bd[t] = FLT_MAX; bi[t] = 0; }
    const float* pp = pd + (size_t)g * SPLIT * KK;
    const int*   ii = pi + (size_t)g * SPLIT * KK;
    for (int c = 0; c < SPLIT * KK; c++) {
        float d = pp[c];
        if (d < bd[KK - 1]) insert16(bd, bi, d, ii[c]);
    }
#pragma unroll
    for (int t = 0; t < KK; t++) idx_out[(size_t)g * KK + t] = bi[t];
}

// ---------------------------------------------------------------------------
// k2: h precompute
// ---------------------------------------------------------------------------
__global__ __launch_bounds__(256)
void h_kernel(const float* __restrict__ xyz, const int* __restrict__ idx,
              const float* __restrict__ w1, const float* __restrict__ b1,
              const float* __restrict__ gamma1, const float* __restrict__ beta1,
              const float* __restrict__ mean1, const float* __restrict__ var1,
              float* __restrict__ H) {
    __shared__ float sw[96], sb[32], ssc[32], ssh[32];
    const int tid = threadIdx.x;
    if (tid < 96) sw[tid] = w1[tid];
    if (tid < 32) {
        sb[tid] = b1[tid];
        float sc = gamma1[tid] * rsqrtf(var1[tid] + BN_EPS);
        ssc[tid] = sc;
        ssh[tid] = beta1[tid] - mean1[tid] * sc;
    }
    __syncthreads();

    const int g0 = blockIdx.x * 16;
    const int p  = tid >> 4;
    const int k  = tid & 15;
    const int g  = g0 + p;
    const int b  = g >> 11;
    const int n  = g & (NN - 1);
    const int nbr = idx[(size_t)g * KK + k];

    const float* qp = xyz + ((size_t)b * NN + n) * 3;
    const float* np = xyz + ((size_t)b * NN + nbr) * 3;
    float qx = qp[0], qy = qp[1], qz = qp[2];
    float px = np[0], py = np[1], pz = np[2];
    float nm = (px != 0.0f || py != 0.0f || pz != 0.0f) ? 1.0f : 0.0f;
    float r0 = nm * (px - qx), r1 = nm * (py - qy), r2 = nm * (pz - qz);

    float* dst = H + (size_t)g * 512 + k * 32;
#pragma unroll
    for (int d4 = 0; d4 < 32; d4 += 4) {
        float4 o;
        float* ov = (float*)&o;
#pragma unroll
        for (int q = 0; q < 4; q++) {
            int d = d4 + q;
            float v = r0 * sw[d] + r1 * sw[32 + d] + r2 * sw[64 + d] + sb[d];
            v = fmaxf(v, 0.0f);
            ov[q] = v * ssc[d] + ssh[d];
        }
        *(float4*)(dst + d4) = o;
    }
}

// ---------------------------------------------------------------------------
// Double-buffered SGEMM: C[M x NMAT] = A[M x KMAT] @ B[KMAT x NMAT].
// BM_ x 128 tile, 8x8 micro, THREADS = BM_*2.
// EPI 0: C = acc + bias[n]   EPI 1: C = relu(acc*sc+sh)*qmask
// ---------------------------------------------------------------------------
template<int BM_, int NMAT, int KMAT, int EPI, int THREADS>
__global__ __launch_bounds__(THREADS)
void sgemm2(const float* __restrict__ A, const float* __restrict__ B,
            const float* __restrict__ e0, const float* __restrict__ e1,
            const float* __restrict__ e2, const float* __restrict__ e3,
            const float* __restrict__ xyz, float* __restrict__ C) {
    constexpr int NT    = KMAT / BKT;
    constexpr int AR    = THREADS / 4;        // A rows per load pass
    constexpr int BSTEP = THREADS / 32;       // B rows per load pass
    constexpr int NBV   = (BKT * BNT) / (4 * THREADS);   // B float4 per thread

    __shared__ float As[2][BKT][BM_];
    __shared__ float Bs[2][BKT][BNT];
    __shared__ float smask[BM_];
    __shared__ float ssc[BNT], ssh[BNT];

    const int tid  = threadIdx.x;
    const int row0 = blockIdx.x * BM_;
    const int col0 = blockIdx.y * BNT;
    const int tx   = tid & 15;
    const int ty   = tid >> 4;
    const int ar   = tid >> 2;
    const int ac   = (tid & 3) * 4;
    const int brr  = tid >> 5;
    const int bcc  = (tid & 31) * 4;

    if (EPI == 1) {
        if (tid < BM_) {
            const float* p = xyz + (size_t)(row0 + tid) * 3;
            smask[tid] = (p[0] != 0.0f || p[1] != 0.0f || p[2] != 0.0f) ? 1.0f : 0.0f;
        }
        if (tid < NMAT) {
            float sc = e0[tid] * rsqrtf(e3[tid] + BN_EPS);
            ssc[tid] = sc;
            ssh[tid] = e1[tid] - e2[tid] * sc;
        }
    }

    unsigned long long acc[8][4];
#pragma unroll
    for (int i = 0; i < 8; i++)
#pragma unroll
        for (int q = 0; q < 4; q++) acc[i][q] = 0ull;

    float4 pa[2];
    float4 pb[NBV];

    // preload tile 0
#pragma unroll
    for (int h = 0; h < 2; h++)
        pa[h] = *(const float4*)(A + (size_t)(row0 + ar + h * AR) * KMAT + ac);
#pragma unroll
    for (int h = 0; h < NBV; h++)
        pb[h] = *(const float4*)(B + (size_t)(brr + h * BSTEP) * NMAT + col0 + bcc);
#pragma unroll
    for (int h = 0; h < 2; h++) {
        As[0][ac + 0][ar + h * AR] = pa[h].x;
        As[0][ac + 1][ar + h * AR] = pa[h].y;
        As[0][ac + 2][ar + h * AR] = pa[h].z;
        As[0][ac + 3][ar + h * AR] = pa[h].w;
    }
#pragma unroll
    for (int h = 0; h < NBV; h++)
        *(float4*)&Bs[0][brr + h * BSTEP][bcc] = pb[h];
    __syncthreads();

#pragma unroll 1
    for (int t = 0; t < NT; t++) {
        const int cur = t & 1;
        if (t + 1 < NT) {
            const int k0 = (t + 1) * BKT;
#pragma unroll
            for (int h = 0; h < 2; h++)
                pa[h] = *(const float4*)(A + (size_t)(row0 + ar + h * AR) * KMAT + k0 + ac);
#pragma unroll
            for (int h = 0; h < NBV; h++)
                pb[h] = *(const float4*)(B + (size_t)(k0 + brr + h * BSTEP) * NMAT + col0 + bcc);
        }

#pragma unroll
        for (int kk = 0; kk < BKT; kk++) {
            float a[8];
            *(float4*)&a[0] = *(const float4*)&As[cur][kk][ty * 8];
            *(float4*)&a[4] = *(const float4*)&As[cur][kk][ty * 8 + 4];
            ulonglong2 bA = *(const ulonglong2*)&Bs[cur][kk][tx * 8];
            ulonglong2 bBv = *(const ulonglong2*)&Bs[cur][kk][tx * 8 + 4];
#pragma unroll
            for (int i = 0; i < 8; i++) {
                unsigned long long a2 = pack2(a[i], a[i]);
                ffma2(acc[i][0], a2, bA.x);
                ffma2(acc[i][1], a2, bA.y);
                ffma2(acc[i][2], a2, bBv.x);
                ffma2(acc[i][3], a2, bBv.y);
            }
        }

        if (t + 1 < NT) {
            const int nxt = cur ^ 1;
#pragma unroll
            for (int h = 0; h < 2; h++) {
                As[nxt][ac + 0][ar + h * AR] = pa[h].x;
                As[nxt][ac + 1][ar + h * AR] = pa[h].y;
                As[nxt][ac + 2][ar + h * AR] = pa[h].z;
                As[nxt][ac + 3][ar + h * AR] = pa[h].w;
            }
#pragma unroll
            for (int h = 0; h < NBV; h++)
                *(float4*)&Bs[nxt][brr + h * BSTEP][bcc] = pb[h];
        }
        __syncthreads();
    }

    // epilogue
    const int crow = row0 + ty * 8;
    const int ccol = col0 + tx * 8;
#pragma unroll
    for (int i = 0; i < 8; i++) {
        float v[8];
#pragma unroll
        for (int q = 0; q < 4; q++) {
            float2 p = unpack2(acc[i][q]);
            v[2 * q] = p.x; v[2 * q + 1] = p.y;
        }
        float* cp = C + (size_t)(crow + i) * NMAT + ccol;
        if (EPI == 0) {
#pragma unroll
            for (int q = 0; q < 8; q++) v[q] += e0[ccol + q];
        } else {
            float m = smask[ty * 8 + i];
#pragma unroll
            for (int q = 0; q < 8; q++) {
                int n = tx * 8 + q;
                v[q] = fmaxf(v[q] * ssc[n] + ssh[n], 0.0f) * m;
            }
        }
        *(float4*)cp       = make_float4(v[0], v[1], v[2], v[3]);
        *(float4*)(cp + 4) = make_float4(v[4], v[5], v[6], v[7]);
    }
}

// ---------------------------------------------------------------------------
// k4: lifted = relu(BN(gather(feat)@wl)) * nmask.
// ---------------------------------------------------------------------------
__global__ __launch_bounds__(256)
void lift_kernel(const float* __restrict__ feat, const int* __restrict__ idx,
                 const float* __restrict__ xyz, const float* __restrict__ wl,
                 const float* __restrict__ gamma_l, const float* __restrict__ beta_l,
                 const float* __restrict__ mean_l, const float* __restrict__ var_l,
                 float* __restrict__ L) {
    extern __shared__ float sm4[];
    float* As    = sm4;             // [64][256] transposed   16384
    float* Bs    = sm4 + 16384;     // [64][64]                4096
    float* smask = sm4 + 20480;     // [256]
    float* ssc   = sm4 + 20736;     // [64]
    float* ssh   = sm4 + 20800;     // [64]

    const int tid  = threadIdx.x;
    const int row0 = blockIdx.x * 256;

    {
        int grow = row0 + tid;
        int nbr  = idx[grow];
        int b    = grow >> 15;
        const float* np = xyz + ((size_t)(b << 11) + nbr) * 3;
        smask[tid] = (np[0] != 0.0f || np[1] != 0.0f || np[2] != 0.0f) ? 1.0f : 0.0f;
        if (tid < 64) {
            float sc = gamma_l[tid] * rsqrtf(var_l[tid] + BN_EPS);
            ssc[tid] = sc;
            ssh[tid] = beta_l[tid] - mean_l[tid] * sc;
        }
    }
    {
        int kr = tid >> 4;
        int cc = (tid & 15) * 4;
#pragma unroll
        for (int h2 = 0; h2 < 4; h2++)
            *(float4*)&Bs[(kr + h2 * 16) * 64 + cc] =
                *(const float4*)(wl + (size_t)(kr + h2 * 16) * 64 + cc);
    }
    {
        int cc = (tid & 15) * 4;
#pragma unroll
        for (int h2 = 0; h2 < 16; h2++) {
            int r    = (tid >> 4) + h2 * 16;
            int grow = row0 + r;
            int nbr  = idx[grow];
            int b    = grow >> 15;
            float4 f = *(const float4*)(feat + ((size_t)(b << 11) + nbr) * 64 + cc);
            As[(cc + 0) * 256 + r] = f.x;
            As[(cc + 1) * 256 + r] = f.y;
            As[(cc + 2) * 256 + r] = f.z;
            As[(cc + 3) * 256 + r] = f.w;
        }
    }
    __syncthreads();

    const int tx = tid & 7;
    const int ty = tid >> 3;
    unsigned long long acc[8][4];
#pragma unroll
    for (int i = 0; i < 8; i++)
#pragma unroll
        for (int q = 0; q < 4; q++) acc[i][q] = 0ull;

#pragma unroll 8
    for (int kk = 0; kk < 64; kk++) {
        float a[8];
        *(float4*)&a[0] = *(const float4*)&As[kk * 256 + ty * 8];
        *(float4*)&a[4] = *(const float4*)&As[kk * 256 + ty * 8 + 4];
        ulonglong2 bA = *(const ulonglong2*)&Bs[kk * 64 + tx * 8];
        ulonglong2 bB = *(const ulonglong2*)&Bs[kk * 64 + tx * 8 + 4];
#pragma unroll
        for (int i = 0; i < 8; i++) {
            unsigned long long a2 = pack2(a[i], a[i]);
            ffma2(acc[i][0], a2, bA.x);
            ffma2(acc[i][1], a2, bA.y);
            ffma2(acc[i][2], a2, bB.x);
            ffma2(acc[i][3], a2, bB.y);
        }
    }

#pragma unroll
    for (int i = 0; i < 8; i++) {
        int rloc = ty * 8 + i;
        int grow = row0 + rloc;
        float m  = smask[rloc];
        float v[8];
#pragma unroll
        for (int q = 0; q < 8; q++) {
            float2 p = unpack2(acc[i][q >> 1]);
            int n = tx * 8 + q;
            float x = ((q & 1) ? p.y : p.x) * ssc[n] + ssh[n];
            v[q] = fmaxf(x, 0.0f) * m;
        }
        float* cp = L + (size_t)grow * 64 + tx * 8;
        *(float4*)cp       = make_float4(v[0], v[1], v[2], v[3]);
        *(float4*)(cp + 4) = make_float4(v[4], v[5], v[6], v[7]);
    }
}

// ---------------------------------------------------------------------------
// k5: transformed[p][i][l] = sum_j X[p][i][j] * lifted[p][j][l].
// ---------------------------------------------------------------------------
__global__ __launch_bounds__(256)
void xform_kernel(const float* __restrict__ X, const float* __restrict__ L,
                  float* __restrict__ T) {
    extern __shared__ float sm5[];
    float* sX = sm5;            // 16*256
    float* sL = sm5 + 4096;     // 16*1024

    const int tid = threadIdx.x;
    const int g0  = blockIdx.x * 16;

    for (int e = tid * 4; e < 4096; e += 1024)
        *(float4*)&sX[e] = *(const float4*)(X + (size_t)g0 * 256 + e);
    for (int e = tid * 4; e < 16384; e += 1024)
        *(float4*)&sL[e] = *(const float4*)(L + (size_t)g0 * 1024 + e);
    __syncthreads();

    const int p = tid >> 4;
    const int i = tid & 15;

    float xr[16];
    {
        const float4* xp = (const float4*)&sX[p * 256 + i * 16];
#pragma unroll
        for (int q = 0; q < 4; q++) *(float4*)&xr[q * 4] = xp[q];
    }

    unsigned long long acc[32];
#pragma unroll
    for (int q = 0; q < 32; q++) acc[q] = 0ull;

#pragma unroll
    for (int j = 0; j < 16; j++) {
        unsigned long long xv = pack2(xr[j], xr[j]);
        const ulonglong2* lp = (const ulonglong2*)&sL[p * 1024 + j * 64];
#pragma unroll
        for (int q = 0; q < 16; q++) {
            ulonglong2 lv = lp[q];
            ffma2(acc[2 * q],     xv, lv.x);
            ffma2(acc[2 * q + 1], xv, lv.y);
        }
    }

    float* dst = T + (size_t)(g0 + p) * 1024 + i * 64;
#pragma unroll
    for (int q = 0; q < 16; q++) {
        float2 a = unpack2(acc[2 * q]);
        float2 b2v = unpack2(acc[2 * q + 1]);
        *(float4*)(dst + q * 4) = make_float4(a.x, a.y, b2v.x, b2v.y);
    }
}

// ---------------------------------------------------------------------------
extern "C" void kernel_launch(void* const* d_in, const int* in_sizes, int n_in,
                              void* d_out, int out_size) {
    const float* xyz     = (const float*)d_in[0];
    const float* feat    = (const float*)d_in[1];
    const float* w1      = (const float*)d_in[2];
    const float* b1      = (const float*)d_in[3];
    const float* gamma1  = (const float*)d_in[4];
    const float* beta1   = (const float*)d_in[5];
    const float* mean1   = (const float*)d_in[6];
    const float* var1    = (const float*)d_in[7];
    const float* w2      = (const float*)d_in[8];
    const float* b2      = (const float*)d_in[9];
    const float* wl      = (const float*)d_in[10];
    const float* gamma_l = (const float*)d_in[11];
    const float* beta_l  = (const float*)d_in[12];
    const float* mean_l  = (const float*)d_in[13];
    const float* var_l   = (const float*)d_in[14];
    const float* wf      = (const float*)d_in[15];
    const float* gamma_f = (const float*)d_in[16];
    const float* beta_f  = (const float*)d_in[17];
    const float* mean_f  = (const float*)d_in[18];
    const float* var_f   = (const float*)d_in[19];
    float* out = (float*)d_out;

    float *pd_ptr, *h_ptr, *X_ptr, *L_ptr, *T_ptr;
    int *pi_ptr, *idx_ptr;
    cudaGetSymbolAddress((void**)&pd_ptr, g_pd);
    cudaGetSymbolAddress((void**)&pi_ptr, g_pi);
    cudaGetSymbolAddress((void**)&idx_ptr, g_idx);
    cudaGetSymbolAddress((void**)&h_ptr, g_h);
    cudaGetSymbolAddress((void**)&X_ptr, g_X);
    cudaGetSymbolAddress((void**)&L_ptr, g_lift);
    cudaGetSymbolAddress((void**)&T_ptr, g_tr);

    knn_part<<<(NPTS / 128) * SPLIT, 128>>>(xyz, pd_ptr, pi_ptr);
    knn_merge<<<NPTS / 128, 128>>>(pd_ptr, pi_ptr, idx_ptr);

    h_kernel<<<NPTS / 16, 256>>>(xyz, idx_ptr, w1, b1, gamma1, beta1,
                                 mean1, var1, h_ptr);

    // k3: X = h @ w2 + b2   (M=16384, N=256, K=512)  BM=128, 256 thr
    sgemm2<128, 256, 512, 0, 256><<<dim3(NPTS / 128, 2), 256>>>(
        h_ptr, w2, b2, nullptr, nullptr, nullptr, xyz, X_ptr);

    // k4: lifted
    cudaFuncSetAttribute(lift_kernel,
                         cudaFuncAttributeMaxDynamicSharedMemorySize, 83456);
    lift_kernel<<<NPTS * 16 / 256, 256, 83456>>>(
        feat, idx_ptr, xyz, wl, gamma_l, beta_l, mean_l, var_l, L_ptr);

    // k5: transformed
    cudaFuncSetAttribute(xform_kernel,
                         cudaFuncAttributeMaxDynamicSharedMemorySize, 81920);
    xform_kernel<<<NPTS / 16, 256, 81920>>>(X_ptr, L_ptr, T_ptr);

    // k6: out = relu(BN(tr @ wf)) * qmask   (M=16384, N=128, K=1024)  BM=64, 128 thr
    sgemm2<64, 128, 1024, 1, 128><<<dim3(NPTS / 64, 1), 128>>>(
        T_ptr, wf, gamma_f, beta_f, mean_f, var_f, xyz, out);
}